// round 4
// baseline (speedup 1.0000x reference)
#include <cuda_runtime.h>
#include <cstdint>

// Problem constants: B=64, S=512, A=8, D=128, C=1024
#define PB  64
#define PS  512
#define PA  8
#define PD  128

#define LEN_BLOCKS 64     // first LEN_BLOCKS blocks compute candidate_len
#define CPW 4             // candidates per warp

// ---------------------------------------------------------------------------
// One kernel, two independent roles (no cross-block communication):
//   blocks [0, 64):   candidate_len for batch b (reads inputs directly).
//   blocks [64, ...): gather — one warp per 4 candidates, MLP-4 pipelined.
// ---------------------------------------------------------------------------
__global__ void __launch_bounds__(256)
cand_kernel(const float*  __restrict__ word_repr,
            const int*    __restrict__ anchor_cls,
            const int*    __restrict__ anchor_loc,
            const int*    __restrict__ cand_idx,
            float*        __restrict__ out,
            long long off_label,
            long long off_mask,
            long long off_loc,
            long long off_len,
            long long off_scalar,   // -1 if absent
            float scalar_val,
            int BC, int C)
{
    if (blockIdx.x < LEN_BLOCKS) {
        // ---- len role: batch = blockIdx.x, reduce mask over C candidates ----
        __shared__ int smem[8];
        int batch = blockIdx.x;
        int base  = batch * C;

        int sum = 0;
        for (int i = threadIdx.x; i < C; i += blockDim.x) {
            int c = base + i;
            int b = cand_idx[3 * c + 0];
            int w = cand_idx[3 * c + 1];
            int a = cand_idx[3 * c + 2];
            long long flat = (((long long)b * PS + w) * PA + a);
            int2 loc = *reinterpret_cast<const int2*>(anchor_loc + flat * 2);
            sum += (loc.x != loc.y) ? 1 : 0;
        }
        #pragma unroll
        for (int o = 16; o > 0; o >>= 1)
            sum += __shfl_down_sync(0xFFFFFFFFu, sum, o);

        int lane = threadIdx.x & 31;
        int wid  = threadIdx.x >> 5;
        if (lane == 0) smem[wid] = sum;
        __syncthreads();
        if (threadIdx.x == 0) {
            int total = 0;
            #pragma unroll
            for (int i = 0; i < 8; i++) total += smem[i];
            out[off_len + batch] = fmaxf((float)total, 1.0f);
            if (batch == 0 && off_scalar >= 0)
                out[off_scalar] = scalar_val;
        }
        return;
    }

    // ---- gather role: one warp handles CPW consecutive candidates ----
    int wid  = threadIdx.x >> 5;
    int lane = threadIdx.x & 31;
    int c0   = (((blockIdx.x - LEN_BLOCKS) * 8) + wid) * CPW;
    if (c0 >= BC) return;

    // One coalesced 48B load of 4 candidates' (b,w,a) triples.
    int val = 0;
    if (lane < 3 * CPW) val = cand_idx[3 * c0 + lane];

    long long flat[CPW];
    #pragma unroll
    for (int j = 0; j < CPW; j++) {
        int b = __shfl_sync(0xFFFFFFFFu, val, 3 * j + 0);
        int w = __shfl_sync(0xFFFFFFFFu, val, 3 * j + 1);
        int a = __shfl_sync(0xFFFFFFFFu, val, 3 * j + 2);
        flat[j] = (((long long)b * PS + w) * PA + a);
    }

    // Issue the 4 big repr loads first (deepest latency, MLP=4).
    float4 v[CPW];
    #pragma unroll
    for (int j = 0; j < CPW; j++)
        v[j] = reinterpret_cast<const float4*>(word_repr + flat[j] * PD)[lane];

    // Lanes 0..3: loc + cls loads in parallel (independent of repr loads).
    int lx = 0, ly = 0, cls = 0;
    if (lane < CPW) {
        int2 loc = *reinterpret_cast<const int2*>(anchor_loc + flat[lane] * 2);
        lx = loc.x; ly = loc.y;
        cls = anchor_cls[flat[lane]];
    }

    float maskj[CPW];
    #pragma unroll
    for (int j = 0; j < CPW; j++) {
        int x = __shfl_sync(0xFFFFFFFFu, lx, j);
        int y = __shfl_sync(0xFFFFFFFFu, ly, j);
        maskj[j] = (x != y) ? 1.0f : 0.0f;
    }

    if (lane < CPW) {
        int c = c0 + lane;
        float m = (lx != ly) ? 1.0f : 0.0f;
        out[off_label + c]       = (float)cls;
        out[off_mask  + c]       = m;
        out[off_loc + 2 * c + 0] = (float)lx;
        out[off_loc + 2 * c + 1] = (float)ly;
    }

    #pragma unroll
    for (int j = 0; j < CPW; j++) {
        float4 t = v[j];
        float m = maskj[j];
        t.x *= m; t.y *= m; t.z *= m; t.w *= m;
        reinterpret_cast<float4*>(out + (long long)(c0 + j) * PD)[lane] = t;
    }
}

// ---------------------------------------------------------------------------
// Host launcher
// ---------------------------------------------------------------------------
extern "C" void kernel_launch(void* const* d_in, const int* in_sizes, int n_in,
                              void* d_out, int out_size)
{
    const float* word_repr  = (const float*)d_in[0];  // (B,S,A,D) fp32
    const int*   anchor_cls = (const int*)d_in[1];    // (B,S,A)   int32
    const int*   anchor_loc = (const int*)d_in[2];    // (B,S,A,2) int32
    const int*   cand_idx   = (const int*)d_in[3];    // (B*C, 3)  int32
    float* out = (float*)d_out;

    int BC = in_sizes[3] / 3;          // 65536
    int C  = BC / PB;                  // 1024

    // Output tuple layout (reference return order):
    //   repr (B*C*D) | label (B*C) | [num (1)] | len (B) | mask (B*C) | loc (B*C*2)
    long long n_repr = (long long)BC * PD;
    long long total_with_scalar = n_repr + BC + 1 + PB + BC + 2LL * BC;

    long long off_label = n_repr;
    long long off_scalar, off_len;
    if ((long long)out_size >= total_with_scalar) {
        off_scalar = off_label + BC;
        off_len    = off_scalar + 1;
    } else {
        off_scalar = -1;
        off_len    = off_label + BC;
    }
    long long off_mask = off_len + PB;
    long long off_loc  = off_mask + BC;

    int threads = 256;                                  // 8 warps/block
    int cand_per_block = 8 * CPW;                       // 32
    int blocks = LEN_BLOCKS + (BC + cand_per_block - 1) / cand_per_block;  // 64 + 2048
    cand_kernel<<<blocks, threads>>>(word_repr, anchor_cls, anchor_loc,
                                     cand_idx, out,
                                     off_label, off_mask, off_loc,
                                     off_len, off_scalar,
                                     (float)C, BC, C);
}

// round 6
// speedup vs baseline: 1.0729x; 1.0729x over previous
#include <cuda_runtime.h>
#include <cstdint>

// Problem constants: B=64, S=512, A=8, D=128, C=1024
#define PB  64
#define PS  512
#define PA  8
#define PD  128

#define LEN_BLOCKS 64   // first LEN_BLOCKS blocks compute candidate_len

// ---------------------------------------------------------------------------
// One kernel, two independent roles (no cross-block communication):
//   blocks [0, 64):      candidate_len for batch b — reads cand_idx+anchor_loc
//                        directly from inputs, full reduction in-block.
//   blocks [64, 64+8192): gather — one warp per candidate, 8 warps/block.
// All output stores use __stcs (evict-first) so the 33 MiB output stream does
// not evict the gathered word_repr rows from L2 between graph replays.
// NOTE: off_len/off_mask/off_loc are ODD element offsets (scalar slot shifts
// them) -> only scalar (4B) stores are legal there. repr region stays 16B OK.
// ---------------------------------------------------------------------------
__global__ void __launch_bounds__(256)
cand_kernel(const float*  __restrict__ word_repr,
            const int*    __restrict__ anchor_cls,
            const int*    __restrict__ anchor_loc,
            const int*    __restrict__ cand_idx,
            float*        __restrict__ out,
            long long off_label,
            long long off_mask,
            long long off_loc,
            long long off_len,
            long long off_scalar,   // -1 if absent
            float scalar_val,
            int BC, int C)
{
    if (blockIdx.x < LEN_BLOCKS) {
        // ---- len role: batch = blockIdx.x, reduce mask over C candidates ----
        __shared__ int smem[8];
        int batch = blockIdx.x;
        int base  = batch * C;

        int sum = 0;
        for (int i = threadIdx.x; i < C; i += blockDim.x) {
            int c = base + i;
            int b = cand_idx[3 * c + 0];
            int w = cand_idx[3 * c + 1];
            int a = cand_idx[3 * c + 2];
            long long flat = (((long long)b * PS + w) * PA + a);
            int2 loc = *reinterpret_cast<const int2*>(anchor_loc + flat * 2);
            sum += (loc.x != loc.y) ? 1 : 0;
        }
        #pragma unroll
        for (int o = 16; o > 0; o >>= 1)
            sum += __shfl_down_sync(0xFFFFFFFFu, sum, o);

        int lane = threadIdx.x & 31;
        int wid  = threadIdx.x >> 5;
        if (lane == 0) smem[wid] = sum;
        __syncthreads();
        if (threadIdx.x == 0) {
            int total = 0;
            #pragma unroll
            for (int i = 0; i < 8; i++) total += smem[i];
            __stcs(out + off_len + batch, fmaxf((float)total, 1.0f));
            if (batch == 0 && off_scalar >= 0)
                __stcs(out + off_scalar, scalar_val);
        }
        return;
    }

    // ---- gather role: one warp per candidate ----
    int wid  = threadIdx.x >> 5;
    int lane = threadIdx.x & 31;
    int warp = (blockIdx.x - LEN_BLOCKS) * 8 + wid;   // candidate index
    if (warp >= BC) return;

    // All lanes read the same 3 ints -> L1 broadcast.
    int b = cand_idx[3 * warp + 0];
    int w = cand_idx[3 * warp + 1];
    int a = cand_idx[3 * warp + 2];

    long long flat = (((long long)b * PS + w) * PA + a);

    // Deepest-latency load first; loc/cls issue independently right after.
    const float4* src = reinterpret_cast<const float4*>(word_repr + flat * PD);
    float4 v = src[lane];

    int2 loc = *reinterpret_cast<const int2*>(anchor_loc + flat * 2);
    float mask = (loc.x != loc.y) ? 1.0f : 0.0f;

    v.x *= mask; v.y *= mask; v.z *= mask; v.w *= mask;
    __stcs(reinterpret_cast<float4*>(out + (long long)warp * PD) + lane, v);

    if (lane == 0) {
        __stcs(out + off_label + warp, (float)anchor_cls[flat]);
        __stcs(out + off_mask  + warp, mask);
        __stcs(out + off_loc + 2 * warp + 0, (float)loc.x);  // scalar: region is
        __stcs(out + off_loc + 2 * warp + 1, (float)loc.y);  // 4B-aligned only
    }
}

// ---------------------------------------------------------------------------
// Host launcher
// ---------------------------------------------------------------------------
extern "C" void kernel_launch(void* const* d_in, const int* in_sizes, int n_in,
                              void* d_out, int out_size)
{
    const float* word_repr  = (const float*)d_in[0];  // (B,S,A,D) fp32
    const int*   anchor_cls = (const int*)d_in[1];    // (B,S,A)   int32
    const int*   anchor_loc = (const int*)d_in[2];    // (B,S,A,2) int32
    const int*   cand_idx   = (const int*)d_in[3];    // (B*C, 3)  int32
    float* out = (float*)d_out;

    int BC = in_sizes[3] / 3;          // 65536
    int C  = BC / PB;                  // 1024

    // Output tuple layout (reference return order):
    //   repr (B*C*D) | label (B*C) | [num (1)] | len (B) | mask (B*C) | loc (B*C*2)
    long long n_repr = (long long)BC * PD;
    long long total_with_scalar = n_repr + BC + 1 + PB + BC + 2LL * BC;

    long long off_label = n_repr;
    long long off_scalar, off_len;
    if ((long long)out_size >= total_with_scalar) {
        off_scalar = off_label + BC;
        off_len    = off_scalar + 1;
    } else {
        off_scalar = -1;
        off_len    = off_label + BC;
    }
    long long off_mask = off_len + PB;
    long long off_loc  = off_mask + BC;

    int threads = 256;                            // 8 warps = 8 candidates/block
    int blocks  = LEN_BLOCKS + (BC + 7) / 8;      // 64 + 8192
    cand_kernel<<<blocks, threads>>>(word_repr, anchor_cls, anchor_loc,
                                     cand_idx, out,
                                     off_label, off_mask, off_loc,
                                     off_len, off_scalar,
                                     (float)C, BC, C);
}

// round 7
// speedup vs baseline: 1.1544x; 1.0760x over previous
#include <cuda_runtime.h>
#include <cstdint>

// Problem constants: B=64, S=512, A=8, D=128, C=1024
#define PB  64
#define PS  512
#define PA  8
#define PD  128

#define LEN_BLOCKS 64   // first LEN_BLOCKS blocks compute candidate_len
#define ITER 8          // candidates per warp (software-pipelined)

// ---------------------------------------------------------------------------
// blocks [0,64):  candidate_len per batch (independent role, reads inputs).
// blocks [64,..): gather — each warp processes ITER consecutive candidates in
//   a ping-pong (depth-2) software pipeline: while stage p's 512B repr load is
//   in flight, stage p^1's small idx/loc/cls loads are issued. Keeps ~2 big
//   loads outstanding per warp (low MLP_p1 -> no L1tex-queue spread penalty)
//   with minimal dead time between them.
// ---------------------------------------------------------------------------
__global__ void __launch_bounds__(256)
cand_kernel(const float*  __restrict__ word_repr,
            const int*    __restrict__ anchor_cls,
            const int*    __restrict__ anchor_loc,
            const int*    __restrict__ cand_idx,
            float*        __restrict__ out,
            long long off_label,
            long long off_mask,
            long long off_loc,
            long long off_len,
            long long off_scalar,   // -1 if absent
            float scalar_val,
            int BC, int C)
{
    if (blockIdx.x < LEN_BLOCKS) {
        // ---- len role ----
        __shared__ int smem[8];
        int batch = blockIdx.x;
        int base  = batch * C;

        int sum = 0;
        for (int i = threadIdx.x; i < C; i += blockDim.x) {
            int c = base + i;
            int b = cand_idx[3 * c + 0];
            int w = cand_idx[3 * c + 1];
            int a = cand_idx[3 * c + 2];
            long long flat = (((long long)b * PS + w) * PA + a);
            int2 loc = *reinterpret_cast<const int2*>(anchor_loc + flat * 2);
            sum += (loc.x != loc.y) ? 1 : 0;
        }
        #pragma unroll
        for (int o = 16; o > 0; o >>= 1)
            sum += __shfl_down_sync(0xFFFFFFFFu, sum, o);

        int lane = threadIdx.x & 31;
        int wid  = threadIdx.x >> 5;
        if (lane == 0) smem[wid] = sum;
        __syncthreads();
        if (threadIdx.x == 0) {
            int total = 0;
            #pragma unroll
            for (int i = 0; i < 8; i++) total += smem[i];
            __stcs(out + off_len + batch, fmaxf((float)total, 1.0f));
            if (batch == 0 && off_scalar >= 0)
                __stcs(out + off_scalar, scalar_val);
        }
        return;
    }

    // ---- gather role: ITER candidates per warp, ping-pong pipeline ----
    int wid  = threadIdx.x >> 5;
    int lane = threadIdx.x & 31;
    int gw   = (blockIdx.x - LEN_BLOCKS) * 8 + wid;   // global warp id
    int c0   = gw * ITER;
    if (c0 >= BC) return;

    long long fl[2];
    float4    vv[2];
    int2      lc[2];
    int       cl[2];

    // Fill stage 0 and stage 1.
    #pragma unroll
    for (int p = 0; p < 2; p++) {
        int c = c0 + p;
        int b = cand_idx[3 * c + 0];
        int w = cand_idx[3 * c + 1];
        int a = cand_idx[3 * c + 2];
        long long flat = (((long long)b * PS + w) * PA + a);
        fl[p] = flat;
        vv[p] = reinterpret_cast<const float4*>(word_repr + flat * PD)[lane];
        lc[p] = *reinterpret_cast<const int2*>(anchor_loc + flat * 2);
        cl[p] = anchor_cls[flat];
    }

    #pragma unroll
    for (int i = 0; i < ITER; i++) {
        int p = i & 1;
        int c = c0 + i;

        // Consume stage p.
        float mask = (lc[p].x != lc[p].y) ? 1.0f : 0.0f;
        float4 t = vv[p];
        t.x *= mask; t.y *= mask; t.z *= mask; t.w *= mask;
        __stcs(reinterpret_cast<float4*>(out + (long long)c * PD) + lane, t);

        if (lane == 0) {
            __stcs(out + off_label + c, (float)cl[p]);
            __stcs(out + off_mask  + c, mask);
            __stcs(out + off_loc + 2 * c + 0, (float)lc[p].x);
            __stcs(out + off_loc + 2 * c + 1, (float)lc[p].y);
        }

        // Refill stage p with candidate c+2 (other stage still in flight).
        if (i + 2 < ITER) {
            int cn = c + 2;
            int b = cand_idx[3 * cn + 0];
            int w = cand_idx[3 * cn + 1];
            int a = cand_idx[3 * cn + 2];
            long long flat = (((long long)b * PS + w) * PA + a);
            fl[p] = flat;
            vv[p] = reinterpret_cast<const float4*>(word_repr + flat * PD)[lane];
            lc[p] = *reinterpret_cast<const int2*>(anchor_loc + flat * 2);
            cl[p] = anchor_cls[flat];
        }
    }
}

// ---------------------------------------------------------------------------
// Host launcher
// ---------------------------------------------------------------------------
extern "C" void kernel_launch(void* const* d_in, const int* in_sizes, int n_in,
                              void* d_out, int out_size)
{
    const float* word_repr  = (const float*)d_in[0];  // (B,S,A,D) fp32
    const int*   anchor_cls = (const int*)d_in[1];    // (B,S,A)   int32
    const int*   anchor_loc = (const int*)d_in[2];    // (B,S,A,2) int32
    const int*   cand_idx   = (const int*)d_in[3];    // (B*C, 3)  int32
    float* out = (float*)d_out;

    int BC = in_sizes[3] / 3;          // 65536
    int C  = BC / PB;                  // 1024

    // Output tuple layout (reference return order):
    //   repr (B*C*D) | label (B*C) | [num (1)] | len (B) | mask (B*C) | loc (B*C*2)
    long long n_repr = (long long)BC * PD;
    long long total_with_scalar = n_repr + BC + 1 + PB + BC + 2LL * BC;

    long long off_label = n_repr;
    long long off_scalar, off_len;
    if ((long long)out_size >= total_with_scalar) {
        off_scalar = off_label + BC;
        off_len    = off_scalar + 1;
    } else {
        off_scalar = -1;
        off_len    = off_label + BC;
    }
    long long off_mask = off_len + PB;
    long long off_loc  = off_mask + BC;

    int threads = 256;                                 // 8 warps/block
    int cand_per_block = 8 * ITER;                     // 64
    int blocks = LEN_BLOCKS + (BC + cand_per_block - 1) / cand_per_block; // 64+1024
    cand_kernel<<<blocks, threads>>>(word_repr, anchor_cls, anchor_loc,
                                     cand_idx, out,
                                     off_label, off_mask, off_loc,
                                     off_len, off_scalar,
                                     (float)C, BC, C);
}

// round 8
// speedup vs baseline: 1.1775x; 1.0200x over previous
#include <cuda_runtime.h>
#include <cstdint>

// Problem constants: B=64, S=512, A=8, D=128, C=1024
#define PB  64
#define PS  512
#define PA  8
#define PD  128

#define LEN_BLOCKS 64   // first LEN_BLOCKS blocks compute candidate_len
#define ITER 8          // candidates per warp (software-pipelined)
#define CPB  64         // candidates per block = 8 warps * ITER

// ---------------------------------------------------------------------------
// blocks [0,64):  candidate_len per batch (independent role, reads inputs).
// blocks [64,..): gather — each warp pipelines ITER candidates (depth-2
//   ping-pong). Small outputs (label/mask/loc) are staged in SMEM and flushed
//   coalesced at block end, removing 4 scattered STG.32 wavefronts/candidate.
// ---------------------------------------------------------------------------
__global__ void __launch_bounds__(256)
cand_kernel(const float*  __restrict__ word_repr,
            const int*    __restrict__ anchor_cls,
            const int*    __restrict__ anchor_loc,
            const int*    __restrict__ cand_idx,
            float*        __restrict__ out,
            long long off_label,
            long long off_mask,
            long long off_loc,
            long long off_len,
            long long off_scalar,   // -1 if absent
            float scalar_val,
            int BC, int C)
{
    if (blockIdx.x < LEN_BLOCKS) {
        // ---- len role ----
        __shared__ int smem[8];
        int batch = blockIdx.x;
        int base  = batch * C;

        int sum = 0;
        for (int i = threadIdx.x; i < C; i += blockDim.x) {
            int c = base + i;
            int b = cand_idx[3 * c + 0];
            int w = cand_idx[3 * c + 1];
            int a = cand_idx[3 * c + 2];
            long long flat = (((long long)b * PS + w) * PA + a);
            int2 loc = *reinterpret_cast<const int2*>(anchor_loc + flat * 2);
            sum += (loc.x != loc.y) ? 1 : 0;
        }
        #pragma unroll
        for (int o = 16; o > 0; o >>= 1)
            sum += __shfl_down_sync(0xFFFFFFFFu, sum, o);

        int lane = threadIdx.x & 31;
        int wid  = threadIdx.x >> 5;
        if (lane == 0) smem[wid] = sum;
        __syncthreads();
        if (threadIdx.x == 0) {
            int total = 0;
            #pragma unroll
            for (int i = 0; i < 8; i++) total += smem[i];
            __stcs(out + off_len + batch, fmaxf((float)total, 1.0f));
            if (batch == 0 && off_scalar >= 0)
                __stcs(out + off_scalar, scalar_val);
        }
        return;
    }

    // ---- gather role ----
    __shared__ float s_label[CPB];
    __shared__ float s_mask [CPB];
    __shared__ float s_locx [CPB];
    __shared__ float s_locy [CPB];

    int wid  = threadIdx.x >> 5;
    int lane = threadIdx.x & 31;
    int cb   = (blockIdx.x - LEN_BLOCKS) * CPB;       // block's first candidate
    int c0   = cb + wid * ITER;                       // this warp's first
    if (c0 >= BC) return;

    float4 vv[2];
    int2   lc[2];
    int    cl[2];

    // Fill stages 0 and 1.
    #pragma unroll
    for (int p = 0; p < 2; p++) {
        int c = c0 + p;
        int b = cand_idx[3 * c + 0];
        int w = cand_idx[3 * c + 1];
        int a = cand_idx[3 * c + 2];
        long long flat = (((long long)b * PS + w) * PA + a);
        vv[p] = reinterpret_cast<const float4*>(word_repr + flat * PD)[lane];
        lc[p] = *reinterpret_cast<const int2*>(anchor_loc + flat * 2);
        cl[p] = anchor_cls[flat];
    }

    #pragma unroll
    for (int i = 0; i < ITER; i++) {
        int p = i & 1;
        int c = c0 + i;

        // Consume stage p.
        float mask = (lc[p].x != lc[p].y) ? 1.0f : 0.0f;
        float4 t = vv[p];
        t.x *= mask; t.y *= mask; t.z *= mask; t.w *= mask;
        __stcs(reinterpret_cast<float4*>(out + (long long)c * PD) + lane, t);

        if (lane == 0) {
            int l = wid * ITER + i;                   // local slot
            s_label[l] = (float)cl[p];
            s_mask [l] = mask;
            s_locx [l] = (float)lc[p].x;
            s_locy [l] = (float)lc[p].y;
        }

        // Refill stage p with candidate c+2.
        if (i + 2 < ITER) {
            int cn = c + 2;
            int b = cand_idx[3 * cn + 0];
            int w = cand_idx[3 * cn + 1];
            int a = cand_idx[3 * cn + 2];
            long long flat = (((long long)b * PS + w) * PA + a);
            vv[p] = reinterpret_cast<const float4*>(word_repr + flat * PD)[lane];
            lc[p] = *reinterpret_cast<const int2*>(anchor_loc + flat * 2);
            cl[p] = anchor_cls[flat];
        }
    }

    __syncthreads();

    // Coalesced flush of the staged small outputs.
    int t = threadIdx.x;
    if (t < CPB) {
        __stcs(out + off_label + cb + t, s_label[t]);
        __stcs(out + off_mask  + cb + t, s_mask[t]);
    }
    if (t < 2 * CPB) {
        // loc region: out[off_loc + 2*cb + t], t covers 128 consecutive floats
        float v = (t & 1) ? s_locy[t >> 1] : s_locx[t >> 1];
        __stcs(out + off_loc + 2 * (long long)cb + t, v);
    }
}

// ---------------------------------------------------------------------------
// Host launcher
// ---------------------------------------------------------------------------
extern "C" void kernel_launch(void* const* d_in, const int* in_sizes, int n_in,
                              void* d_out, int out_size)
{
    const float* word_repr  = (const float*)d_in[0];  // (B,S,A,D) fp32
    const int*   anchor_cls = (const int*)d_in[1];    // (B,S,A)   int32
    const int*   anchor_loc = (const int*)d_in[2];    // (B,S,A,2) int32
    const int*   cand_idx   = (const int*)d_in[3];    // (B*C, 3)  int32
    float* out = (float*)d_out;

    int BC = in_sizes[3] / 3;          // 65536
    int C  = BC / PB;                  // 1024

    // Output tuple layout (reference return order):
    //   repr (B*C*D) | label (B*C) | [num (1)] | len (B) | mask (B*C) | loc (B*C*2)
    long long n_repr = (long long)BC * PD;
    long long total_with_scalar = n_repr + BC + 1 + PB + BC + 2LL * BC;

    long long off_label = n_repr;
    long long off_scalar, off_len;
    if ((long long)out_size >= total_with_scalar) {
        off_scalar = off_label + BC;
        off_len    = off_scalar + 1;
    } else {
        off_scalar = -1;
        off_len    = off_label + BC;
    }
    long long off_mask = off_len + PB;
    long long off_loc  = off_mask + BC;

    int threads = 256;                                        // 8 warps/block
    int blocks  = LEN_BLOCKS + (BC + CPB - 1) / CPB;          // 64 + 1024
    cand_kernel<<<blocks, threads>>>(word_repr, anchor_cls, anchor_loc,
                                     cand_idx, out,
                                     off_label, off_mask, off_loc,
                                     off_len, off_scalar,
                                     (float)C, BC, C);
}

// round 9
// speedup vs baseline: 1.1805x; 1.0025x over previous
#include <cuda_runtime.h>
#include <cstdint>

// Problem constants: B=64, S=512, A=8, D=128, C=1024
#define PB  64
#define PS  512
#define PA  8
#define PD  128

#define LEN_BLOCKS 64   // first LEN_BLOCKS blocks compute candidate_len
#define ITER 8          // candidates per warp
#define CPB  64         // candidates per block = 8 warps * ITER
#define STAGES 4        // cp.async pipeline depth

__device__ __forceinline__ void cpasync16(uint32_t dst_smem, const void* src) {
    asm volatile("cp.async.cg.shared.global [%0], [%1], 16;"
                 :: "r"(dst_smem), "l"(src));
}
__device__ __forceinline__ void cpcommit() {
    asm volatile("cp.async.commit_group;");
}
__device__ __forceinline__ void cpwait3() {
    asm volatile("cp.async.wait_group 3;");
}
__device__ __forceinline__ void cpwait0() {
    asm volatile("cp.async.wait_group 0;");
}

// ---------------------------------------------------------------------------
// blocks [0,64):  candidate_len per batch (independent role, reads inputs).
// blocks [64,..): gather — 8 warps x 8 candidates. Per warp: all 8 flat
//   indices computed up front (coalesced idx load + shuffles); repr rows are
//   staged into SMEM via cp.async (depth-4 groups) so load latency never
//   touches the register scoreboard; consume = LDS.128 -> mask -> STG.128.
// ---------------------------------------------------------------------------
__global__ void __launch_bounds__(256)
cand_kernel(const float*  __restrict__ word_repr,
            const int*    __restrict__ anchor_cls,
            const int*    __restrict__ anchor_loc,
            const int*    __restrict__ cand_idx,
            float*        __restrict__ out,
            long long off_label,
            long long off_mask,
            long long off_loc,
            long long off_len,
            long long off_scalar,   // -1 if absent
            float scalar_val,
            int BC, int C)
{
    if (blockIdx.x < LEN_BLOCKS) {
        // ---- len role ----
        __shared__ int rsm[8];
        int batch = blockIdx.x;
        int base  = batch * C;

        int sum = 0;
        for (int i = threadIdx.x; i < C; i += blockDim.x) {
            int c = base + i;
            int b = cand_idx[3 * c + 0];
            int w = cand_idx[3 * c + 1];
            int a = cand_idx[3 * c + 2];
            long long flat = (((long long)b * PS + w) * PA + a);
            int2 loc = *reinterpret_cast<const int2*>(anchor_loc + flat * 2);
            sum += (loc.x != loc.y) ? 1 : 0;
        }
        #pragma unroll
        for (int o = 16; o > 0; o >>= 1)
            sum += __shfl_down_sync(0xFFFFFFFFu, sum, o);

        int lane = threadIdx.x & 31;
        int wid  = threadIdx.x >> 5;
        if (lane == 0) rsm[wid] = sum;
        __syncthreads();
        if (threadIdx.x == 0) {
            int total = 0;
            #pragma unroll
            for (int i = 0; i < 8; i++) total += rsm[i];
            __stcs(out + off_len + batch, fmaxf((float)total, 1.0f));
            if (batch == 0 && off_scalar >= 0)
                __stcs(out + off_scalar, scalar_val);
        }
        return;
    }

    // ---- gather role ----
    __shared__ __align__(16) float s_stage[8][STAGES][PD]; // 16 KB
    __shared__ float s_label[CPB];
    __shared__ float s_mask [CPB];
    __shared__ float s_locx [CPB];
    __shared__ float s_locy [CPB];

    int wid  = threadIdx.x >> 5;
    int lane = threadIdx.x & 31;
    int cb   = (blockIdx.x - LEN_BLOCKS) * CPB;
    int c0   = cb + wid * ITER;

    // --- prologue: all 8 flats via one coalesced idx load + shuffles ---
    int val = 0;
    if (lane < 3 * ITER) val = cand_idx[3 * c0 + lane];

    // lane j (j<8) computes flat for candidate c0+j
    int bb = __shfl_sync(0xFFFFFFFFu, val, (lane < 8) ? 3 * lane + 0 : 0);
    int ww = __shfl_sync(0xFFFFFFFFu, val, (lane < 8) ? 3 * lane + 1 : 0);
    int aa = __shfl_sync(0xFFFFFFFFu, val, (lane < 8) ? 3 * lane + 2 : 0);
    long long myflat = (((long long)bb * PS + ww) * PA + aa);
    int flat_lo = (int)(myflat & 0xFFFFFFFFll);
    int flat_hi = (int)(myflat >> 32);

    uint32_t stage_base = (uint32_t)__cvta_generic_to_shared(&s_stage[wid][0][0]);

    // Issue first STAGES cp.async groups (flat[i] via shuffle from lane i).
    #pragma unroll
    for (int i = 0; i < STAGES; i++) {
        int lo = __shfl_sync(0xFFFFFFFFu, flat_lo, i);
        int hi = __shfl_sync(0xFFFFFFFFu, flat_hi, i);
        long long fl = ((long long)hi << 32) | (unsigned int)lo;
        const float* src = word_repr + fl * PD + lane * 4;
        cpasync16(stage_base + (uint32_t)(i * PD * 4) + lane * 16, src);
        cpcommit();
    }

    // loc/cls for my candidate (lanes 0..7), overlapping the cp.asyncs.
    float mymask = 0.0f;
    if (lane < ITER) {
        int2 loc = *reinterpret_cast<const int2*>(anchor_loc + myflat * 2);
        int  cls = anchor_cls[myflat];
        mymask = (loc.x != loc.y) ? 1.0f : 0.0f;
        int l = wid * ITER + lane;
        s_label[l] = (float)cls;
        s_mask [l] = mymask;
        s_locx [l] = (float)loc.x;
        s_locy [l] = (float)loc.y;
    }

    // --- main pipeline ---
    #pragma unroll
    for (int i = 0; i < ITER; i++) {
        cpwait3();                       // stage i complete
        int slot = i & (STAGES - 1);

        float mask = __shfl_sync(0xFFFFFFFFu, mymask, i);
        float4 t = *reinterpret_cast<float4*>(&s_stage[wid][slot][lane * 4]);
        t.x *= mask; t.y *= mask; t.z *= mask; t.w *= mask;
        __stcs(reinterpret_cast<float4*>(out + (long long)(c0 + i) * PD) + lane, t);

        if (i + STAGES < ITER) {
            int lo = __shfl_sync(0xFFFFFFFFu, flat_lo, i + STAGES);
            int hi = __shfl_sync(0xFFFFFFFFu, flat_hi, i + STAGES);
            long long fl = ((long long)hi << 32) | (unsigned int)lo;
            const float* src = word_repr + fl * PD + lane * 4;
            cpasync16(stage_base + (uint32_t)(slot * PD * 4) + lane * 16, src);
        }
        cpcommit();                      // empty commit in tail keeps count math fixed
    }
    cpwait0();

    __syncthreads();

    // Coalesced flush of the staged small outputs.
    int t = threadIdx.x;
    if (t < CPB) {
        __stcs(out + off_label + cb + t, s_label[t]);
        __stcs(out + off_mask  + cb + t, s_mask[t]);
    }
    if (t < 2 * CPB) {
        float v = (t & 1) ? s_locy[t >> 1] : s_locx[t >> 1];
        __stcs(out + off_loc + 2 * (long long)cb + t, v);
    }
}

// ---------------------------------------------------------------------------
// Host launcher
// ---------------------------------------------------------------------------
extern "C" void kernel_launch(void* const* d_in, const int* in_sizes, int n_in,
                              void* d_out, int out_size)
{
    const float* word_repr  = (const float*)d_in[0];  // (B,S,A,D) fp32
    const int*   anchor_cls = (const int*)d_in[1];    // (B,S,A)   int32
    const int*   anchor_loc = (const int*)d_in[2];    // (B,S,A,2) int32
    const int*   cand_idx   = (const int*)d_in[3];    // (B*C, 3)  int32
    float* out = (float*)d_out;

    int BC = in_sizes[3] / 3;          // 65536
    int C  = BC / PB;                  // 1024

    // Output tuple layout (reference return order):
    //   repr (B*C*D) | label (B*C) | [num (1)] | len (B) | mask (B*C) | loc (B*C*2)
    long long n_repr = (long long)BC * PD;
    long long total_with_scalar = n_repr + BC + 1 + PB + BC + 2LL * BC;

    long long off_label = n_repr;
    long long off_scalar, off_len;
    if ((long long)out_size >= total_with_scalar) {
        off_scalar = off_label + BC;
        off_len    = off_scalar + 1;
    } else {
        off_scalar = -1;
        off_len    = off_label + BC;
    }
    long long off_mask = off_len + PB;
    long long off_loc  = off_mask + BC;

    int threads = 256;                                        // 8 warps/block
    int blocks  = LEN_BLOCKS + (BC + CPB - 1) / CPB;          // 64 + 1024
    cand_kernel<<<blocks, threads>>>(word_repr, anchor_cls, anchor_loc,
                                     cand_idx, out,
                                     off_label, off_mask, off_loc,
                                     off_len, off_scalar,
                                     (float)C, BC, C);
}